// round 16
// baseline (speedup 1.0000x reference)
#include <cuda_runtime.h>
#include <math_constants.h>

// Problem constants (fixed by the reference setup)
#define BB   4
#define NN   32768
#define KK   16
#define DD   8
#define TOT  (BB * NN * KK)        // 2,097,152 per channel
#define GRPS (TOT / 4)             // 524,288 groups of 4 along K
#define TPB  256
#define NBLKR 512                  // repack: 512x256 = 131072 = BB*NN threads
#define NBSF  512                  // stats+feat blocks (grid-stride, 4 iters/thread)
#define SF_ITERS (GRPS / (NBSF * TPB))   // 4
#define NBLKC (GRPS / TPB)         // 2048 conv blocks
#define EPSF 1e-6f

// Device-global scratch (no allocation allowed)
__device__ float  g_partS[DD][NBSF];    // per-block partial sums (contention-free)
__device__ float  g_partQ[DD][NBSF];    // per-block partial square-sums
__device__ float  g_scale[DD];
__device__ float  g_shift[DD];
__device__ unsigned int g_ctr;          // completion counter (monotone, replay-safe)
__device__ float4 g_c4[BB * NN];        // repacked coords (2 MB, L2-resident)

__device__ __forceinline__ int clamp_idx(int v) {
    v = v < 0 ? 0 : v;
    return v >= NN ? NN - 1 : v;
}

// ---- Kernel 1: coords repack (tiny; publishes g_c4 via kernel boundary) ----
__global__ void __launch_bounds__(TPB) k_repack(const float* __restrict__ coords) {
    const int i = blockIdx.x * TPB + threadIdx.x;   // 0 .. BB*NN-1
    float x = coords[3 * i + 0];
    float y = coords[3 * i + 1];
    float z = coords[3 * i + 2];
    g_c4[i] = make_float4(x, y, z, 0.f);
}

// ---- Kernel 2: BN statistics + feature broadcast (channels 8..15, 64 MB) ----
// Grid-stride, 4 group-iterations per thread. The feature-channel stores fill
// the bandwidth/issue slots the gather latency chain leaves idle.
// Contention-free fp32 partials; last-arriving block finalizes scale/shift.
__global__ void __launch_bounds__(TPB) k_stats_feat(
    const float* __restrict__ features,    // (B,D,N,1)
    const int* __restrict__ knn_idx,       // (B,N,K) int32
    const float* __restrict__ knn_dist,    // (B,N,K)
    const int* __restrict__ mask,          // (B,N)
    const float* __restrict__ conv_w,      // (D,10)
    const float* __restrict__ conv_b,      // (D)
    const float* __restrict__ bn_gamma,
    const float* __restrict__ bn_beta,
    float* __restrict__ out)               // (B,2D,N,K)
{
    __shared__ float s_wn0[DD], s_wn1[DD], s_wn2[DD], s_wdd[DD];
    __shared__ float s_wc0[DD], s_wc1[DD], s_wc2[DD], s_b[DD];
    __shared__ float s_part[TPB / 32][2 * DD];
    __shared__ bool  s_last;
    __shared__ double s_fin[2 * DD][16 + 1];
    __shared__ double s_tot[2 * DD];

    const int tid = threadIdx.x;
    const int gid = blockIdx.x * TPB + tid;

    if (tid < DD) {
        const float* w = conv_w + tid * 10;
        float w0=w[0], w1=w[1], w2=w[2], w3=w[3], w4=w[4];
        float w5=w[5], w6=w[6], w7=w[7], w8=w[8];
        s_wn0[tid] = w3 - w6;  s_wn1[tid] = w4 - w7;  s_wn2[tid] = w5 - w8;
        s_wdd[tid] = w[9];
        s_wc0[tid] = w0 + w6;  s_wc1[tid] = w1 + w7;  s_wc2[tid] = w2 + w8;
        s_b[tid]   = conv_b[tid];
    }
    __syncthreads();

    float s[DD], q[DD];
#pragma unroll
    for (int d = 0; d < DD; d++) { s[d] = 0.f; q[d] = 0.f; }

#pragma unroll 1
    for (int it = 0; it < SF_ITERS; it++) {
        const int g  = it * (NBSF * TPB) + gid;
        const int e0 = g * 4;
        const int b  = e0 >> 19;
        const int rm = e0 & ((NN * KK) - 1);
        const int n  = rm >> 4;
        const int k0 = rm & (KK - 1);

        const float4 c = g_c4[b * NN + n];

        int4 iv = *reinterpret_cast<const int4*>(knn_idx + e0);
        int j0 = clamp_idx(iv.x), j1 = clamp_idx(iv.y);
        int j2 = clamp_idx(iv.z), j3 = clamp_idx(iv.w);

        float4 d4 = *reinterpret_cast<const float4*>(knn_dist + e0);
        float dv0 = d4.x, dv1 = d4.y, dv2 = d4.z, dv3 = d4.w;
        if (mask[b * NN + n] == 0) {
            dv0 = dv1 = dv2 = dv3 = CUDART_INF_F;
        }

        float4 p0 = g_c4[b * NN + j0];
        float4 p1 = g_c4[b * NN + j1];
        float4 p2 = g_c4[b * NN + j2];
        float4 p3 = g_c4[b * NN + j3];

        // Feature broadcast stores for this (b, n, k0..k0+3) — fills idle BW.
        const size_t obase = ((size_t)b * (2 * DD) + DD) * NN * KK
                           + (size_t)n * KK + k0;
#pragma unroll
        for (int d = 0; d < DD; d++) {
            float fv = features[((size_t)b * DD + d) * NN + n];
            float4 o = {fv, fv, fv, fv};
            *reinterpret_cast<float4*>(out + obase + (size_t)d * NN * KK) = o;
        }

        // Statistics accumulation.
#pragma unroll
        for (int d = 0; d < DD; d++) {
            float base = s_b[d] + s_wc0[d]*c.x + s_wc1[d]*c.y + s_wc2[d]*c.z;
            float x0 = base + s_wn0[d]*p0.x + s_wn1[d]*p0.y + s_wn2[d]*p0.z + s_wdd[d]*dv0;
            float x1 = base + s_wn0[d]*p1.x + s_wn1[d]*p1.y + s_wn2[d]*p1.z + s_wdd[d]*dv1;
            float x2 = base + s_wn0[d]*p2.x + s_wn1[d]*p2.y + s_wn2[d]*p2.z + s_wdd[d]*dv2;
            float x3 = base + s_wn0[d]*p3.x + s_wn1[d]*p3.y + s_wn2[d]*p3.z + s_wdd[d]*dv3;
            s[d] += (x0 + x1) + (x2 + x3);
            q[d] = fmaf(x0, x0, q[d]);
            q[d] = fmaf(x1, x1, q[d]);
            q[d] = fmaf(x2, x2, q[d]);
            q[d] = fmaf(x3, x3, q[d]);
        }
    }

    // Warp reduction -> block partials -> plain stores to distinct slots.
#pragma unroll
    for (int d = 0; d < DD; d++) {
#pragma unroll
        for (int o = 16; o > 0; o >>= 1) {
            s[d] += __shfl_xor_sync(0xFFFFFFFFu, s[d], o);
            q[d] += __shfl_xor_sync(0xFFFFFFFFu, q[d], o);
        }
    }
    const int warp = tid >> 5;
    const int lane = tid & 31;
    if (lane == 0) {
#pragma unroll
        for (int d = 0; d < DD; d++) {
            s_part[warp][d]      = s[d];
            s_part[warp][DD + d] = q[d];
        }
    }
    __syncthreads();
    if (tid < 2 * DD) {
        float acc = 0.f;
#pragma unroll
        for (int w = 0; w < TPB / 32; w++) acc += s_part[w][tid];
        if (tid < DD)
            g_partS[tid][blockIdx.x] = acc;
        else
            g_partQ[tid - DD][blockIdx.x] = acc;
    }

    // Monotone completion counter; last-arriving BLOCK finalizes in parallel.
    __threadfence();
    __syncthreads();
    if (tid == 0) {
        unsigned prev = atomicAdd(&g_ctr, 1u);
        s_last = (prev % NBSF == NBSF - 1);
    }
    __syncthreads();
    if (!s_last) return;

    // Finalize: 256 threads = 16 quantities x 16 slices of NBSF/16 partials.
    {
        const int qty   = tid & 15;        // 0..7 = S[d], 8..15 = Q[d-8]
        const int slice = tid >> 4;        // 0..15
        const float* row = (qty < DD) ? &g_partS[qty][0] : &g_partQ[qty - DD][0];
        const int base = slice * (NBSF / 16);
        float a0 = 0.f, a1 = 0.f, a2 = 0.f, a3 = 0.f;
#pragma unroll 4
        for (int i = 0; i < NBSF / 16; i += 4) {
            a0 += row[base + i + 0];
            a1 += row[base + i + 1];
            a2 += row[base + i + 2];
            a3 += row[base + i + 3];
        }
        s_fin[qty][slice] = ((double)a0 + (double)a1) + ((double)a2 + (double)a3);
    }
    __syncthreads();
    if (tid < 2 * DD) {
        double t = 0.0;
#pragma unroll
        for (int sl = 0; sl < 16; sl++) t += s_fin[tid][sl];
        s_tot[tid] = t;
    }
    __syncthreads();
    if (tid < DD) {
        double mean = s_tot[tid] * (1.0 / (double)TOT);
        double var  = s_tot[DD + tid] * (1.0 / (double)TOT) - mean * mean;
        float rstd  = rsqrtf((float)var + EPSF);
        float sc    = bn_gamma[tid] * rstd;
        g_scale[tid] = sc;
        g_shift[tid] = bn_beta[tid] - (float)mean * sc;
    }
}

// ---- Kernel 3: conv+BN+relu channels [0..7] (64 MB) ----
__global__ void __launch_bounds__(TPB, 3) k_conv(
    const int* __restrict__ knn_idx,
    const float* __restrict__ knn_dist,
    const int* __restrict__ mask,
    const float* __restrict__ conv_w,
    const float* __restrict__ conv_b,
    float* __restrict__ out)               // (B,2D,N,K)
{
    __shared__ float s_wn0[DD], s_wn1[DD], s_wn2[DD], s_wdd[DD];
    __shared__ float s_wc0[DD], s_wc1[DD], s_wc2[DD], s_b[DD];
    __shared__ float s_sc[DD], s_sh[DD];

    const int tid = threadIdx.x;
    if (tid < DD) {
        const float* w = conv_w + tid * 10;
        float w0=w[0], w1=w[1], w2=w[2], w3=w[3], w4=w[4];
        float w5=w[5], w6=w[6], w7=w[7], w8=w[8];
        s_wn0[tid] = w3 - w6;  s_wn1[tid] = w4 - w7;  s_wn2[tid] = w5 - w8;
        s_wdd[tid] = w[9];
        s_wc0[tid] = w0 + w6;  s_wc1[tid] = w1 + w7;  s_wc2[tid] = w2 + w8;
        s_b[tid]   = conv_b[tid];
        s_sc[tid]  = g_scale[tid];
        s_sh[tid]  = g_shift[tid];
    }
    __syncthreads();

    const int g  = blockIdx.x * TPB + tid;
    const int e0 = g * 4;
    const int b  = e0 >> 19;
    const int rm = e0 & ((NN * KK) - 1);
    const int n  = rm >> 4;
    const int k0 = rm & (KK - 1);

    const float4 c = g_c4[b * NN + n];

    int4 iv = *reinterpret_cast<const int4*>(knn_idx + e0);
    int j0 = clamp_idx(iv.x), j1 = clamp_idx(iv.y);
    int j2 = clamp_idx(iv.z), j3 = clamp_idx(iv.w);

    float4 d4 = *reinterpret_cast<const float4*>(knn_dist + e0);
    float dv0 = d4.x, dv1 = d4.y, dv2 = d4.z, dv3 = d4.w;
    if (mask[b * NN + n] == 0) {
        dv0 = dv1 = dv2 = dv3 = CUDART_INF_F;
    }

    float4 p0 = g_c4[b * NN + j0];
    float4 p1 = g_c4[b * NN + j1];
    float4 p2 = g_c4[b * NN + j2];
    float4 p3 = g_c4[b * NN + j3];

    const size_t obase = ((size_t)b * (2 * DD)) * NN * KK + (size_t)n * KK + k0;
#pragma unroll
    for (int d = 0; d < DD; d++) {
        float base = s_b[d] + s_wc0[d]*c.x + s_wc1[d]*c.y + s_wc2[d]*c.z;
        float x0 = base + s_wn0[d]*p0.x + s_wn1[d]*p0.y + s_wn2[d]*p0.z + s_wdd[d]*dv0;
        float x1 = base + s_wn0[d]*p1.x + s_wn1[d]*p1.y + s_wn2[d]*p1.z + s_wdd[d]*dv1;
        float x2 = base + s_wn0[d]*p2.x + s_wn1[d]*p2.y + s_wn2[d]*p2.z + s_wdd[d]*dv2;
        float x3 = base + s_wn0[d]*p3.x + s_wn1[d]*p3.y + s_wn2[d]*p3.z + s_wdd[d]*dv3;
        float4 o;
        o.x = fmaxf(fmaf(x0, s_sc[d], s_sh[d]), 0.f);
        o.y = fmaxf(fmaf(x1, s_sc[d], s_sh[d]), 0.f);
        o.z = fmaxf(fmaf(x2, s_sc[d], s_sh[d]), 0.f);
        o.w = fmaxf(fmaf(x3, s_sc[d], s_sh[d]), 0.f);
        *reinterpret_cast<float4*>(out + obase + (size_t)d * NN * KK) = o;
    }
}

extern "C" void kernel_launch(void* const* d_in, const int* in_sizes, int n_in,
                              void* d_out, int out_size) {
    const float* coords   = (const float*)d_in[0];
    const float* features = (const float*)d_in[1];
    const int*   knn_idx  = (const int*)d_in[2];
    const float* knn_dist = (const float*)d_in[3];
    const int*   mask     = (const int*)d_in[4];
    const float* conv_w   = (const float*)d_in[5];
    const float* conv_b   = (const float*)d_in[6];
    const float* bn_gamma = (const float*)d_in[7];
    const float* bn_beta  = (const float*)d_in[8];
    float*       out      = (float*)d_out;

    // Ordering via kernel boundaries: repack publishes g_c4; stats_feat
    // publishes scale/shift (and writes channels 8..15); conv writes 0..7.
    k_repack<<<NBLKR, TPB>>>(coords);
    k_stats_feat<<<NBSF, TPB>>>(features, knn_idx, knn_dist, mask,
                                conv_w, conv_b, bn_gamma, bn_beta, out);
    k_conv<<<NBLKC, TPB>>>(knn_idx, knn_dist, mask, conv_w, conv_b, out);
}

// round 17
// speedup vs baseline: 1.5305x; 1.5305x over previous
#include <cuda_runtime.h>
#include <math_constants.h>

// Problem constants (fixed by the reference setup)
#define BB   4
#define NN   32768
#define KK   16
#define DD   8
#define TOT  (BB * NN * KK)        // 2,097,152 per channel
#define GRPS (TOT / 4)             // 524,288 groups of 4 along K
#define TPB  256
#define NBLKR 512                  // repack blocks (1 point/thread)
#define NBSF  256                  // stats blocks (grid-stride, 8 iters/thread)
#define SF_ITERS (GRPS / (NBSF * TPB))   // 8
#define NBLKC (GRPS / TPB)         // 2048 conv blocks
#define NBLKF 2048                 // feature blocks (8 float4 slots/thread)
#define FITERS 8
#define EPSF 1e-6f

// Device-global scratch (no allocation allowed)
__device__ float  g_partS[DD][NBSF];    // per-block partial sums (contention-free)
__device__ float  g_partQ[DD][NBSF];    // per-block partial square-sums
__device__ float  g_scale[DD];
__device__ float  g_shift[DD];
__device__ unsigned int g_ctr;          // completion counter (monotone, replay-safe)
__device__ float4 g_c4[BB * NN];        // repacked coords (2 MB, L2-resident)

__device__ __forceinline__ int clamp_idx(int v) {
    v = v < 0 ? 0 : v;
    return v >= NN ? NN - 1 : v;
}

// ---- coords repack (publishes g_c4 via kernel boundary) ----
__global__ void __launch_bounds__(TPB) k_repack(const float* __restrict__ coords) {
    const int i = blockIdx.x * TPB + threadIdx.x;   // 0 .. BB*NN-1
    float x = coords[3 * i + 0];
    float y = coords[3 * i + 1];
    float z = coords[3 * i + 2];
    g_c4[i] = make_float4(x, y, z, 0.f);
}

// ---- BN statistics: 256-block grid-stride (best-measured stats shape) ----
// Contention-free fp32 partials; last-arriving block finalizes scale/shift.
__global__ void __launch_bounds__(TPB) k_stats(
    const int* __restrict__ knn_idx,       // (B,N,K) int32
    const float* __restrict__ knn_dist,    // (B,N,K)
    const int* __restrict__ mask,          // (B,N)
    const float* __restrict__ conv_w,      // (D,10)
    const float* __restrict__ conv_b,      // (D)
    const float* __restrict__ bn_gamma,
    const float* __restrict__ bn_beta)
{
    __shared__ float s_wn0[DD], s_wn1[DD], s_wn2[DD], s_wdd[DD];
    __shared__ float s_wc0[DD], s_wc1[DD], s_wc2[DD], s_b[DD];
    __shared__ float s_part[TPB / 32][2 * DD];
    __shared__ bool  s_last;
    __shared__ double s_fin[2 * DD][16 + 1];
    __shared__ double s_tot[2 * DD];

    const int tid = threadIdx.x;
    const int gid = blockIdx.x * TPB + tid;

    if (tid < DD) {
        const float* w = conv_w + tid * 10;
        float w0=w[0], w1=w[1], w2=w[2], w3=w[3], w4=w[4];
        float w5=w[5], w6=w[6], w7=w[7], w8=w[8];
        s_wn0[tid] = w3 - w6;  s_wn1[tid] = w4 - w7;  s_wn2[tid] = w5 - w8;
        s_wdd[tid] = w[9];
        s_wc0[tid] = w0 + w6;  s_wc1[tid] = w1 + w7;  s_wc2[tid] = w2 + w8;
        s_b[tid]   = conv_b[tid];
    }
    __syncthreads();

    float s[DD], q[DD];
#pragma unroll
    for (int d = 0; d < DD; d++) { s[d] = 0.f; q[d] = 0.f; }

#pragma unroll 1
    for (int it = 0; it < SF_ITERS; it++) {
        const int g  = it * (NBSF * TPB) + gid;
        const int e0 = g * 4;
        const int b  = e0 >> 19;
        const int rm = e0 & ((NN * KK) - 1);
        const int n  = rm >> 4;

        const float4 c = g_c4[b * NN + n];

        int4 iv = *reinterpret_cast<const int4*>(knn_idx + e0);
        int j0 = clamp_idx(iv.x), j1 = clamp_idx(iv.y);
        int j2 = clamp_idx(iv.z), j3 = clamp_idx(iv.w);

        float4 d4 = *reinterpret_cast<const float4*>(knn_dist + e0);
        float dv0 = d4.x, dv1 = d4.y, dv2 = d4.z, dv3 = d4.w;
        if (mask[b * NN + n] == 0) {
            dv0 = dv1 = dv2 = dv3 = CUDART_INF_F;
        }

        float4 p0 = g_c4[b * NN + j0];
        float4 p1 = g_c4[b * NN + j1];
        float4 p2 = g_c4[b * NN + j2];
        float4 p3 = g_c4[b * NN + j3];

#pragma unroll
        for (int d = 0; d < DD; d++) {
            float base = s_b[d] + s_wc0[d]*c.x + s_wc1[d]*c.y + s_wc2[d]*c.z;
            float x0 = base + s_wn0[d]*p0.x + s_wn1[d]*p0.y + s_wn2[d]*p0.z + s_wdd[d]*dv0;
            float x1 = base + s_wn0[d]*p1.x + s_wn1[d]*p1.y + s_wn2[d]*p1.z + s_wdd[d]*dv1;
            float x2 = base + s_wn0[d]*p2.x + s_wn1[d]*p2.y + s_wn2[d]*p2.z + s_wdd[d]*dv2;
            float x3 = base + s_wn0[d]*p3.x + s_wn1[d]*p3.y + s_wn2[d]*p3.z + s_wdd[d]*dv3;
            s[d] += (x0 + x1) + (x2 + x3);
            q[d] = fmaf(x0, x0, q[d]);
            q[d] = fmaf(x1, x1, q[d]);
            q[d] = fmaf(x2, x2, q[d]);
            q[d] = fmaf(x3, x3, q[d]);
        }
    }

    // Warp reduction -> block partials -> plain stores to distinct slots.
#pragma unroll
    for (int d = 0; d < DD; d++) {
#pragma unroll
        for (int o = 16; o > 0; o >>= 1) {
            s[d] += __shfl_xor_sync(0xFFFFFFFFu, s[d], o);
            q[d] += __shfl_xor_sync(0xFFFFFFFFu, q[d], o);
        }
    }
    const int warp = tid >> 5;
    const int lane = tid & 31;
    if (lane == 0) {
#pragma unroll
        for (int d = 0; d < DD; d++) {
            s_part[warp][d]      = s[d];
            s_part[warp][DD + d] = q[d];
        }
    }
    __syncthreads();
    if (tid < 2 * DD) {
        float acc = 0.f;
#pragma unroll
        for (int w = 0; w < TPB / 32; w++) acc += s_part[w][tid];
        if (tid < DD)
            g_partS[tid][blockIdx.x] = acc;
        else
            g_partQ[tid - DD][blockIdx.x] = acc;
    }

    // Monotone completion counter; last-arriving BLOCK finalizes in parallel.
    __threadfence();
    __syncthreads();
    if (tid == 0) {
        unsigned prev = atomicAdd(&g_ctr, 1u);
        s_last = (prev % NBSF == NBSF - 1);
    }
    __syncthreads();
    if (!s_last) return;

    // Finalize: 256 threads = 16 quantities x 16 slices of NBSF/16 partials.
    {
        const int qty   = tid & 15;        // 0..7 = S[d], 8..15 = Q[d-8]
        const int slice = tid >> 4;        // 0..15
        const float* row = (qty < DD) ? &g_partS[qty][0] : &g_partQ[qty - DD][0];
        const int base = slice * (NBSF / 16);
        float a0 = 0.f, a1 = 0.f, a2 = 0.f, a3 = 0.f;
#pragma unroll
        for (int i = 0; i < NBSF / 16; i += 4) {
            a0 += row[base + i + 0];
            a1 += row[base + i + 1];
            a2 += row[base + i + 2];
            a3 += row[base + i + 3];
        }
        s_fin[qty][slice] = ((double)a0 + (double)a1) + ((double)a2 + (double)a3);
    }
    __syncthreads();
    if (tid < 2 * DD) {
        double t = 0.0;
#pragma unroll
        for (int sl = 0; sl < 16; sl++) t += s_fin[tid][sl];
        s_tot[tid] = t;
    }
    __syncthreads();
    if (tid < DD) {
        double mean = s_tot[tid] * (1.0 / (double)TOT);
        double var  = s_tot[DD + tid] * (1.0 / (double)TOT) - mean * mean;
        float rstd  = rsqrtf((float)var + EPSF);
        float sc    = bn_gamma[tid] * rstd;
        g_scale[tid] = sc;
        g_shift[tid] = bn_beta[tid] - (float)mean * sc;
    }
}

// ---- conv+BN+relu channels [0..7] (64 MB) ----
__global__ void __launch_bounds__(TPB, 3) k_conv(
    const int* __restrict__ knn_idx,
    const float* __restrict__ knn_dist,
    const int* __restrict__ mask,
    const float* __restrict__ conv_w,
    const float* __restrict__ conv_b,
    float* __restrict__ out)               // (B,2D,N,K)
{
    __shared__ float s_wn0[DD], s_wn1[DD], s_wn2[DD], s_wdd[DD];
    __shared__ float s_wc0[DD], s_wc1[DD], s_wc2[DD], s_b[DD];
    __shared__ float s_sc[DD], s_sh[DD];

    const int tid = threadIdx.x;
    if (tid < DD) {
        const float* w = conv_w + tid * 10;
        float w0=w[0], w1=w[1], w2=w[2], w3=w[3], w4=w[4];
        float w5=w[5], w6=w[6], w7=w[7], w8=w[8];
        s_wn0[tid] = w3 - w6;  s_wn1[tid] = w4 - w7;  s_wn2[tid] = w5 - w8;
        s_wdd[tid] = w[9];
        s_wc0[tid] = w0 + w6;  s_wc1[tid] = w1 + w7;  s_wc2[tid] = w2 + w8;
        s_b[tid]   = conv_b[tid];
        s_sc[tid]  = g_scale[tid];
        s_sh[tid]  = g_shift[tid];
    }
    __syncthreads();

    const int g  = blockIdx.x * TPB + tid;
    const int e0 = g * 4;
    const int b  = e0 >> 19;
    const int rm = e0 & ((NN * KK) - 1);
    const int n  = rm >> 4;
    const int k0 = rm & (KK - 1);

    const float4 c = g_c4[b * NN + n];

    int4 iv = *reinterpret_cast<const int4*>(knn_idx + e0);
    int j0 = clamp_idx(iv.x), j1 = clamp_idx(iv.y);
    int j2 = clamp_idx(iv.z), j3 = clamp_idx(iv.w);

    float4 d4 = *reinterpret_cast<const float4*>(knn_dist + e0);
    float dv0 = d4.x, dv1 = d4.y, dv2 = d4.z, dv3 = d4.w;
    if (mask[b * NN + n] == 0) {
        dv0 = dv1 = dv2 = dv3 = CUDART_INF_F;
    }

    float4 p0 = g_c4[b * NN + j0];
    float4 p1 = g_c4[b * NN + j1];
    float4 p2 = g_c4[b * NN + j2];
    float4 p3 = g_c4[b * NN + j3];

    const size_t obase = ((size_t)b * (2 * DD)) * NN * KK + (size_t)n * KK + k0;
#pragma unroll
    for (int d = 0; d < DD; d++) {
        float base = s_b[d] + s_wc0[d]*c.x + s_wc1[d]*c.y + s_wc2[d]*c.z;
        float x0 = base + s_wn0[d]*p0.x + s_wn1[d]*p0.y + s_wn2[d]*p0.z + s_wdd[d]*dv0;
        float x1 = base + s_wn0[d]*p1.x + s_wn1[d]*p1.y + s_wn2[d]*p1.z + s_wdd[d]*dv1;
        float x2 = base + s_wn0[d]*p2.x + s_wn1[d]*p2.y + s_wn2[d]*p2.z + s_wdd[d]*dv2;
        float x3 = base + s_wn0[d]*p3.x + s_wn1[d]*p3.y + s_wn2[d]*p3.z + s_wdd[d]*dv3;
        float4 o;
        o.x = fmaxf(fmaf(x0, s_sc[d], s_sh[d]), 0.f);
        o.y = fmaxf(fmaf(x1, s_sc[d], s_sh[d]), 0.f);
        o.z = fmaxf(fmaf(x2, s_sc[d], s_sh[d]), 0.f);
        o.w = fmaxf(fmaf(x3, s_sc[d], s_sh[d]), 0.f);
        *reinterpret_cast<float4*>(out + obase + (size_t)d * NN * KK) = o;
    }
}

// ---- feature broadcast channels [8..15] (64 MB): fully independent ----
__global__ void __launch_bounds__(TPB) k_feat(
    const float* __restrict__ features,    // (B,D,N,1)
    float* __restrict__ out)               // (B,2D,N,K)
{
    const int t0 = blockIdx.x * TPB + threadIdx.x;
#pragma unroll
    for (int it = 0; it < FITERS; it++) {
        const int g = it * (NBLKF * TPB) + t0;   // 0 .. 4,194,303 float4 slots
        const int k4 = g & 3;
        const int n  = (g >> 2) & (NN - 1);
        const int d  = (g >> 17) & (DD - 1);
        const int b  = g >> 20;
        float fv = features[((size_t)b * DD + d) * NN + n];
        float4 o = {fv, fv, fv, fv};
        const size_t off = ((size_t)b * (2 * DD) + (DD + d)) * NN * KK
                         + (size_t)n * KK + k4 * 4;
        *reinterpret_cast<float4*>(out + off) = o;
    }
}

extern "C" void kernel_launch(void* const* d_in, const int* in_sizes, int n_in,
                              void* d_out, int out_size) {
    const float* coords   = (const float*)d_in[0];
    const float* features = (const float*)d_in[1];
    const int*   knn_idx  = (const int*)d_in[2];
    const float* knn_dist = (const float*)d_in[3];
    const int*   mask     = (const int*)d_in[4];
    const float* conv_w   = (const float*)d_in[5];
    const float* conv_b   = (const float*)d_in[6];
    const float* bn_gamma = (const float*)d_in[7];
    const float* bn_beta  = (const float*)d_in[8];
    float*       out      = (float*)d_out;

    // Lazily created ONCE on the (non-captured) correctness call; reused during
    // capture. Host-side objects only — no device memory allocation.
    static cudaStream_t s2 = nullptr;
    static cudaEvent_t evFork = nullptr, evJoin = nullptr;
    if (s2 == nullptr) {
        cudaStreamCreateWithFlags(&s2, cudaStreamNonBlocking);
        cudaEventCreateWithFlags(&evFork, cudaEventDisableTiming);
        cudaEventCreateWithFlags(&evJoin, cudaEventDisableTiming);
    }

    // Fork: feat (independent; writes channels 8..15) runs concurrently with
    // repack -> stats on the main stream. Join before returning so the
    // captured graph is fully connected.
    cudaEventRecord(evFork, 0);
    cudaStreamWaitEvent(s2, evFork, 0);
    k_feat<<<NBLKF, TPB, 0, s2>>>(features, out);
    cudaEventRecord(evJoin, s2);

    k_repack<<<NBLKR, TPB>>>(coords);
    k_stats<<<NBSF, TPB>>>(knn_idx, knn_dist, mask, conv_w, conv_b,
                           bn_gamma, bn_beta);
    k_conv<<<NBLKC, TPB>>>(knn_idx, knn_dist, mask, conv_w, conv_b, out);

    cudaStreamWaitEvent(0, evJoin, 0);
}